// round 3
// baseline (speedup 1.0000x reference)
#include <cuda_runtime.h>
#include <cuda_bf16.h>
#include <mma.h>

using namespace nvcuda;

// Problem constants
#define BB   512
#define TT   128
#define DIN  256
#define HH   1024
#define FH   4096           // 4*HH
#define TBROWS (TT*BB)      // 65536
#define LBL  3

// GEMM tiling
#define BM 128
#define BN 128
#define BK 32
#define ASTRIDE (BK+8)      // 40 (conflict-free for ldmatrix)
#define BSTRIDE (BN+8)      // 136

// ---------------- scratch (device globals: no allocation allowed) ----------
__device__ float d_Xtm[(size_t)TBROWS*DIN];     // time-major input  [T*B, 256]
__device__ float d_Z[(size_t)TBROWS*FH];        // pre-activations   [T*B, 4096] (reused for both layers)
__device__ float d_H1all[(size_t)TBROWS*HH];    // layer-1 hidden states, all timesteps
__device__ float d_h1[BB*HH], d_c1[BB*HH];
__device__ float d_h2[BB*HH], d_c2[BB*HH];
__device__ float d_hidden[BB*HH];               // gathered last-valid h2 per batch

// bf16 split weights (hi/lo)
__device__ __nv_bfloat16 d_W1h[(size_t)DIN*FH], d_W1l[(size_t)DIN*FH];
__device__ __nv_bfloat16 d_U1h[(size_t)HH*FH],  d_U1l[(size_t)HH*FH];
__device__ __nv_bfloat16 d_W2h[(size_t)HH*FH],  d_W2l[(size_t)HH*FH];
__device__ __nv_bfloat16 d_U2h[(size_t)HH*FH],  d_U2l[(size_t)HH*FH];

// ---------------- helper kernels -------------------------------------------

// split fp32 weight matrix into bf16 hi/lo pair
__global__ void split_weight(const float* __restrict__ W,
                             __nv_bfloat16* __restrict__ hi,
                             __nv_bfloat16* __restrict__ lo, int n)
{
    int i = blockIdx.x * blockDim.x + threadIdx.x;
    if (i < n) {
        float x = W[i];
        __nv_bfloat16 h = __float2bfloat16(x);
        hi[i] = h;
        lo[i] = __float2bfloat16(x - __bfloat162float(h));
    }
}

// chars [B][T][DIN] -> Xtm [T][B][DIN]  (float4 granularity)
__global__ void transpose_chars(const float* __restrict__ chars, float* __restrict__ Xtm)
{
    int idx = blockIdx.x * blockDim.x + threadIdx.x;  // over TBROWS*DIN/4
    int d4 = idx & (DIN/4 - 1);
    int rest = idx >> 6;                // / (DIN/4)
    int b = rest & (BB - 1);
    int t = rest >> 9;                  // / BB
    const float4* src = (const float4*)chars;
    float4* dst = (float4*)Xtm;
    dst[((size_t)t*BB + b)*(DIN/4) + d4] = src[((size_t)b*TT + t)*(DIN/4) + d4];
}

__global__ void init_states()
{
    int i = blockIdx.x * blockDim.x + threadIdx.x;
    if (i < BB*HH) { d_h1[i] = 0.f; d_c1[i] = 0.f; d_h2[i] = 0.f; d_c2[i] = 0.f; }
}

// LSTM gate elementwise: z [B,4H] (i,f,g,o keras order), c/h [B,H]
__global__ void lstm_gate(const float* __restrict__ z, const float* __restrict__ bias,
                          float* __restrict__ c, float* __restrict__ h,
                          float* __restrict__ hstore,        // layer1: H1all+t*B*H, else null
                          const int* __restrict__ seqlen,    // layer2: gather, else null
                          float* __restrict__ hidden, int t)
{
    int i = blockIdx.x * blockDim.x + threadIdx.x;  // B*H
    int b = i >> 10;
    int j = i & (HH - 1);
    const float* zr = z + (size_t)b * FH;
    float zi = zr[j]        + bias[j];
    float zf = zr[HH + j]   + bias[HH + j];
    float zg = zr[2*HH + j] + bias[2*HH + j];
    float zo = zr[3*HH + j] + bias[3*HH + j];
    float ig = 1.f / (1.f + __expf(-zi));
    float fg = 1.f / (1.f + __expf(-zf));
    float gg = tanhf(zg);
    float og = 1.f / (1.f + __expf(-zo));
    float cn = fg * c[i] + ig * gg;
    c[i] = cn;
    float hn = og * tanhf(cn);
    h[i] = hn;
    if (hstore) hstore[i] = hn;
    if (seqlen && (seqlen[b] - 1 == t)) hidden[i] = hn;
}

// out[b,:] = relu(hidden[b,:] @ Wd + bd)
__global__ void dense_relu(const float* __restrict__ hidden, const float* __restrict__ Wd,
                           const float* __restrict__ bd, float* __restrict__ out)
{
    __shared__ float buf[3][128];
    int b = blockIdx.x, tid = threadIdx.x;
    const float* hb = hidden + (size_t)b * HH;
    float s0 = 0.f, s1 = 0.f, s2 = 0.f;
    for (int k = tid; k < HH; k += 128) {
        float hv = hb[k];
        s0 = fmaf(hv, Wd[k*3 + 0], s0);
        s1 = fmaf(hv, Wd[k*3 + 1], s1);
        s2 = fmaf(hv, Wd[k*3 + 2], s2);
    }
    buf[0][tid] = s0; buf[1][tid] = s1; buf[2][tid] = s2;
    __syncthreads();
    for (int s = 64; s > 0; s >>= 1) {
        if (tid < s) {
            buf[0][tid] += buf[0][tid + s];
            buf[1][tid] += buf[1][tid + s];
            buf[2][tid] += buf[2][tid + s];
        }
        __syncthreads();
    }
    if (tid < 3) out[b*3 + tid] = fmaxf(buf[tid][0] + bd[tid], 0.f);
}

// ---------------- split-bf16 (3-MMA) GEMM ----------------------------------
// C[M,N] (+)= A[M,K] @ B[K,N], A fp32 (split on the fly), B pre-split bf16 hi/lo.
// CTA tile 128x128, BK=32, 8 warps as 2x4 (warp tile 64x32), two-stage pipeline.
__global__ void __launch_bounds__(256)
gemm_bf16x3(const float* __restrict__ A,
            const __nv_bfloat16* __restrict__ Bh, const __nv_bfloat16* __restrict__ Bl,
            float* __restrict__ C, int M, int N, int K, int accumulate)
{
    __shared__ __nv_bfloat16 sAh[BM][ASTRIDE];
    __shared__ __nv_bfloat16 sAl[BM][ASTRIDE];
    __shared__ __nv_bfloat16 sBh[BK][BSTRIDE];
    __shared__ __nv_bfloat16 sBl[BK][BSTRIDE];

    const int bm = blockIdx.y * BM;
    const int bn = blockIdx.x * BN;
    const int tid = threadIdx.x;
    const int warp = tid >> 5;
    const int wr = warp >> 2;   // 0..1 -> 64 rows
    const int wc = warp & 3;    // 0..3 -> 32 cols

    wmma::fragment<wmma::accumulator, 16, 16, 16, float> acc[4][2];
    if (accumulate) {
        #pragma unroll
        for (int m = 0; m < 4; m++)
            #pragma unroll
            for (int n = 0; n < 2; n++)
                wmma::load_matrix_sync(acc[m][n],
                    &C[(size_t)(bm + wr*64 + m*16)*N + bn + wc*32 + n*16],
                    N, wmma::mem_row_major);
    } else {
        #pragma unroll
        for (int m = 0; m < 4; m++)
            #pragma unroll
            for (int n = 0; n < 2; n++)
                wmma::fill_fragment(acc[m][n], 0.0f);
    }

    float4 aReg[4];
    uint4  bhReg[2], blReg[2];

    auto loadG = [&](int k0) {
        #pragma unroll
        for (int i = 0; i < 4; i++) {
            int idx = tid + (i << 8);
            int r = idx >> 3, c = (idx & 7) << 2;
            aReg[i] = *(const float4*)(A + (size_t)(bm + r)*K + k0 + c);
        }
        #pragma unroll
        for (int i = 0; i < 2; i++) {
            int idx = tid + (i << 8);
            int r = idx >> 4, c = (idx & 15) << 3;
            bhReg[i] = *(const uint4*)(Bh + (size_t)(k0 + r)*N + bn + c);
            blReg[i] = *(const uint4*)(Bl + (size_t)(k0 + r)*N + bn + c);
        }
    };
    auto storeS = [&]() {
        #pragma unroll
        for (int i = 0; i < 4; i++) {
            int idx = tid + (i << 8);
            int r = idx >> 3, c = (idx & 7) << 2;
            float vx = aReg[i].x, vy = aReg[i].y, vz = aReg[i].z, vw = aReg[i].w;
            __nv_bfloat16 hx = __float2bfloat16(vx), hy = __float2bfloat16(vy);
            __nv_bfloat16 hz = __float2bfloat16(vz), hw = __float2bfloat16(vw);
            __nv_bfloat162 hp0; hp0.x = hx; hp0.y = hy;
            __nv_bfloat162 hp1; hp1.x = hz; hp1.y = hw;
            *(__nv_bfloat162*)&sAh[r][c]     = hp0;
            *(__nv_bfloat162*)&sAh[r][c + 2] = hp1;
            __nv_bfloat162 lp0, lp1;
            lp0.x = __float2bfloat16(vx - __bfloat162float(hx));
            lp0.y = __float2bfloat16(vy - __bfloat162float(hy));
            lp1.x = __float2bfloat16(vz - __bfloat162float(hz));
            lp1.y = __float2bfloat16(vw - __bfloat162float(hw));
            *(__nv_bfloat162*)&sAl[r][c]     = lp0;
            *(__nv_bfloat162*)&sAl[r][c + 2] = lp1;
        }
        #pragma unroll
        for (int i = 0; i < 2; i++) {
            int idx = tid + (i << 8);
            int r = idx >> 4, c = (idx & 15) << 3;
            *(uint4*)&sBh[r][c] = bhReg[i];
            *(uint4*)&sBl[r][c] = blReg[i];
        }
    };
    auto compute = [&]() {
        #pragma unroll
        for (int kk = 0; kk < 2; kk++) {
            wmma::fragment<wmma::matrix_b, 16, 16, 16, __nv_bfloat16, wmma::row_major> fbh[2], fbl[2];
            #pragma unroll
            for (int n = 0; n < 2; n++) {
                wmma::load_matrix_sync(fbh[n], &sBh[kk*16][wc*32 + n*16], BSTRIDE);
                wmma::load_matrix_sync(fbl[n], &sBl[kk*16][wc*32 + n*16], BSTRIDE);
            }
            #pragma unroll
            for (int m = 0; m < 4; m++) {
                wmma::fragment<wmma::matrix_a, 16, 16, 16, __nv_bfloat16, wmma::row_major> fah, fal;
                wmma::load_matrix_sync(fah, &sAh[wr*64 + m*16][kk*16], ASTRIDE);
                wmma::load_matrix_sync(fal, &sAl[wr*64 + m*16][kk*16], ASTRIDE);
                #pragma unroll
                for (int n = 0; n < 2; n++) {
                    wmma::mma_sync(acc[m][n], fah, fbh[n], acc[m][n]);
                    wmma::mma_sync(acc[m][n], fal, fbh[n], acc[m][n]);
                    wmma::mma_sync(acc[m][n], fah, fbl[n], acc[m][n]);
                }
            }
        }
    };

    loadG(0);
    storeS();
    __syncthreads();
    for (int k0 = BK; k0 <= K; k0 += BK) {
        bool more = (k0 < K);
        if (more) loadG(k0);
        compute();
        if (more) {
            __syncthreads();
            storeS();
            __syncthreads();
        }
    }

    #pragma unroll
    for (int m = 0; m < 4; m++)
        #pragma unroll
        for (int n = 0; n < 2; n++)
            wmma::store_matrix_sync(&C[(size_t)(bm + wr*64 + m*16)*N + bn + wc*32 + n*16],
                                    acc[m][n], N, wmma::mem_row_major);
}

// ---------------- launch ----------------------------------------------------
extern "C" void kernel_launch(void* const* d_in, const int* in_sizes, int n_in,
                              void* d_out, int out_size)
{
    const float* chars  = (const float*)d_in[0];
    const int*   seqlen = (const int*)  d_in[1];
    const float* W1 = (const float*)d_in[2];
    const float* U1 = (const float*)d_in[3];
    const float* b1 = (const float*)d_in[4];
    const float* W2 = (const float*)d_in[5];
    const float* U2 = (const float*)d_in[6];
    const float* b2 = (const float*)d_in[7];
    const float* Wd = (const float*)d_in[8];
    const float* bd = (const float*)d_in[9];
    float* out = (float*)d_out;

    float *Xtm, *Z, *H1all, *h1, *c1, *h2, *c2, *hidden;
    __nv_bfloat16 *W1h, *W1l, *U1h, *U1l, *W2h, *W2l, *U2h, *U2l;
    cudaGetSymbolAddress((void**)&Xtm,    d_Xtm);
    cudaGetSymbolAddress((void**)&Z,      d_Z);
    cudaGetSymbolAddress((void**)&H1all,  d_H1all);
    cudaGetSymbolAddress((void**)&h1,     d_h1);
    cudaGetSymbolAddress((void**)&c1,     d_c1);
    cudaGetSymbolAddress((void**)&h2,     d_h2);
    cudaGetSymbolAddress((void**)&c2,     d_c2);
    cudaGetSymbolAddress((void**)&hidden, d_hidden);
    cudaGetSymbolAddress((void**)&W1h, d_W1h); cudaGetSymbolAddress((void**)&W1l, d_W1l);
    cudaGetSymbolAddress((void**)&U1h, d_U1h); cudaGetSymbolAddress((void**)&U1l, d_U1l);
    cudaGetSymbolAddress((void**)&W2h, d_W2h); cudaGetSymbolAddress((void**)&W2l, d_W2l);
    cudaGetSymbolAddress((void**)&U2h, d_U2h); cudaGetSymbolAddress((void**)&U2l, d_U2l);

    // weight splits (cheap, done each launch for determinism)
    split_weight<<<(DIN*FH + 255)/256, 256>>>(W1, W1h, W1l, DIN*FH);
    split_weight<<<(HH*FH  + 255)/256, 256>>>(U1, U1h, U1l, HH*FH);
    split_weight<<<(HH*FH  + 255)/256, 256>>>(W2, W2h, W2l, HH*FH);
    split_weight<<<(HH*FH  + 255)/256, 256>>>(U2, U2h, U2l, HH*FH);

    transpose_chars<<<(TBROWS*DIN/4)/256, 256>>>(chars, Xtm);
    init_states<<<(BB*HH)/256, 256>>>();

    dim3 blk(256);
    dim3 gBig(FH/BN, TBROWS/BM);   // (32, 512)
    dim3 gStep(FH/BN, BB/BM);      // (32, 4)
    const int gateBlocks = (BB*HH)/256;  // 2048

    // layer 1 input transform: Z = Xtm @ W1
    gemm_bf16x3<<<gBig, blk>>>(Xtm, W1h, W1l, Z, TBROWS, FH, DIN, 0);

    // layer 1 recurrence
    for (int t = 0; t < TT; t++) {
        float* zt = Z + (size_t)t * BB * FH;
        gemm_bf16x3<<<gStep, blk>>>(h1, U1h, U1l, zt, BB, FH, HH, 1);
        lstm_gate<<<gateBlocks, 256>>>(zt, b1, c1, h1,
                                       H1all + (size_t)t * BB * HH, nullptr, nullptr, t);
    }

    // layer 2 input transform: Z = H1all @ W2 (reuse Z)
    gemm_bf16x3<<<gBig, blk>>>(H1all, W2h, W2l, Z, TBROWS, FH, HH, 0);

    // layer 2 recurrence + last-valid gather
    for (int t = 0; t < TT; t++) {
        float* zt = Z + (size_t)t * BB * FH;
        gemm_bf16x3<<<gStep, blk>>>(h2, U2h, U2l, zt, BB, FH, HH, 1);
        lstm_gate<<<gateBlocks, 256>>>(zt, b2, c2, h2,
                                       nullptr, seqlen, hidden, t);
    }

    dense_relu<<<BB, 128>>>(hidden, Wd, bd, out);
}

// round 5
// speedup vs baseline: 1.0925x; 1.0925x over previous
#include <cuda_runtime.h>
#include <cuda_bf16.h>
#include <mma.h>
#include <cstdint>

using namespace nvcuda;

#define BB   512
#define TT   128
#define DIN  256
#define HH   1024
#define FH   4096
#define TBROWS (TT*BB)

#define OPB 10240u            // one operand stage: 128 rows * 80 bytes
#define OPE 5120              // same in bf16 elements
#define STG 40960u            // 4 operands per stage (bytes)
#define SMEM_DYN (4*40960)    // 4 stages = 160 KB
#define LDS_EP 132            // epilogue smem stride (floats)

// ------------- device scratch (no allocation allowed) -------------
__device__ float d_Z[(size_t)TBROWS*FH];
__device__ float d_c1[BB*HH], d_c2[BB*HH];
__device__ float d_hidden[BB*HH];
__device__ float d_b1i[FH], d_b2i[FH];
__device__ __nv_bfloat16 d_Xh[(size_t)TBROWS*DIN], d_Xl[(size_t)TBROWS*DIN];
__device__ __nv_bfloat16 d_H1h[(size_t)(TT+1)*BB*HH], d_H1l[(size_t)(TT+1)*BB*HH];
__device__ __nv_bfloat16 d_H2h[(size_t)(TT+1)*BB*HH], d_H2l[(size_t)(TT+1)*BB*HH];
__device__ __nv_bfloat16 d_W1h[(size_t)FH*DIN], d_W1l[(size_t)FH*DIN];
__device__ __nv_bfloat16 d_U1h[(size_t)FH*HH],  d_U1l[(size_t)FH*HH];
__device__ __nv_bfloat16 d_W2h[(size_t)FH*HH],  d_W2l[(size_t)FH*HH];
__device__ __nv_bfloat16 d_U2h[(size_t)FH*HH],  d_U2l[(size_t)FH*HH];

// ------------- PTX helpers (Ampere-level only: valid on sm_103 plain) ------
__device__ __forceinline__ uint32_t smem_u32(const void* p) {
    uint32_t a;
    asm("{ .reg .u64 t; cvta.to.shared.u64 t, %1; cvt.u32.u64 %0, t; }" : "=r"(a) : "l"(p));
    return a;
}
__device__ __forceinline__ void cp16(uint32_t d, const void* s) {
    asm volatile("cp.async.cg.shared.global [%0], [%1], 16;" :: "r"(d), "l"(s) : "memory");
}
__device__ __forceinline__ void cp_commit() { asm volatile("cp.async.commit_group;" ::: "memory"); }
__device__ __forceinline__ void cp_wait2()  { asm volatile("cp.async.wait_group 2;" ::: "memory"); }

// ------------- preprocessing -------------
// W [K, 4H] -> Wt[n=j*4+gate][k], split hi/lo bf16
__global__ void split_w(const float* __restrict__ W, __nv_bfloat16* __restrict__ oh,
                        __nv_bfloat16* __restrict__ ol, int K)
{
    size_t i = (size_t)blockIdx.x * blockDim.x + threadIdx.x;
    int k = (int)(i % K), n = (int)(i / K);
    float x = W[(size_t)k * FH + (n & 3) * HH + (n >> 2)];
    __nv_bfloat16 h = __float2bfloat16(x);
    oh[i] = h;
    ol[i] = __float2bfloat16(x - __bfloat162float(h));
}
__global__ void interleave_bias(const float* __restrict__ b, float* __restrict__ bi)
{
    int n = blockIdx.x * blockDim.x + threadIdx.x;
    bi[n] = b[(n & 3) * HH + (n >> 2)];
}
// chars [B][T][256] -> split bf16 time-major [t*B+b][256]
__global__ void split_chars(const float* __restrict__ chars,
                            __nv_bfloat16* __restrict__ xh, __nv_bfloat16* __restrict__ xl)
{
    int idx = blockIdx.x * blockDim.x + threadIdx.x;   // TBROWS*64
    int d4 = idx & 63, rest = idx >> 6;
    int b = rest & (BB - 1), t = rest >> 9;
    float4 v = *(const float4*)(chars + ((size_t)b * TT + t) * DIN + d4 * 4);
    size_t o = ((size_t)t * BB + b) * DIN + d4 * 4;
    float vv[4] = {v.x, v.y, v.z, v.w};
    #pragma unroll
    for (int e = 0; e < 4; e++) {
        __nv_bfloat16 h = __float2bfloat16(vv[e]);
        xh[o + e] = h;
        xl[o + e] = __float2bfloat16(vv[e] - __bfloat162float(h));
    }
}
__global__ void init_states()
{
    int i = blockIdx.x * blockDim.x + threadIdx.x;  // BB*HH
    d_c1[i] = 0.f; d_c2[i] = 0.f;
    __nv_bfloat16 z = __float2bfloat16(0.f);
    d_H1h[i] = z; d_H1l[i] = z; d_H2h[i] = z; d_H2l[i] = z;
}
__global__ void dense_relu(const float* __restrict__ hidden, const float* __restrict__ Wd,
                           const float* __restrict__ bd, float* __restrict__ out)
{
    __shared__ float buf[3][128];
    int b = blockIdx.x, tid = threadIdx.x;
    const float* hb = hidden + (size_t)b * HH;
    float s0 = 0.f, s1 = 0.f, s2 = 0.f;
    for (int k = tid; k < HH; k += 128) {
        float hv = hb[k];
        s0 = fmaf(hv, Wd[k*3+0], s0); s1 = fmaf(hv, Wd[k*3+1], s1); s2 = fmaf(hv, Wd[k*3+2], s2);
    }
    buf[0][tid] = s0; buf[1][tid] = s1; buf[2][tid] = s2;
    __syncthreads();
    for (int s = 64; s > 0; s >>= 1) {
        if (tid < s) { buf[0][tid]+=buf[0][tid+s]; buf[1][tid]+=buf[1][tid+s]; buf[2][tid]+=buf[2][tid+s]; }
        __syncthreads();
    }
    if (tid < 3) out[b*3 + tid] = fmaxf(buf[tid][0] + bd[tid], 0.f);
}

// ------------- pipelined HMMA GEMM + optional fused LSTM gate epilogue -----
// D[128,128] = A[128,K] @ B[128,K]^T  (both K-major, hi/lo split, 3 MMA terms)
// mode 0: Z[row,n] = D.   mode 1: z = D + Z + bias -> gates -> c,h(split bf16).
__global__ void __launch_bounds__(256, 1)
lstm_gemm(const __nv_bfloat16* __restrict__ Ah, const __nv_bfloat16* __restrict__ Al,
          const __nv_bfloat16* __restrict__ Bh, const __nv_bfloat16* __restrict__ Bl,
          int K, float* __restrict__ Z, int mode,
          const float* __restrict__ biasI, float* __restrict__ cst,
          __nv_bfloat16* __restrict__ hh, __nv_bfloat16* __restrict__ hl,
          const int* __restrict__ seqlen, float* __restrict__ hidden, int t)
{
    extern __shared__ char smem[];
    const int tid = threadIdx.x, wid = tid >> 5;
    const int wr = wid & 3, wc = wid >> 2;          // 4 row groups x 2 col groups
    const int bx = blockIdx.x, by = blockIdx.y;
    const int nch = K >> 5;
    const uint32_t sbase = smem_u32(smem);

    const __nv_bfloat16* srcs[4] = {Ah, Al, Bh, Bl};
    const int rb[4] = {by*128, by*128, bx*128, bx*128};

    auto load_chunk = [&](int ch, int buf) {
        if (ch < nch) {
            const int k0 = ch << 5;
            const uint32_t st = sbase + (uint32_t)buf * STG;
            #pragma unroll
            for (int op = 0; op < 4; op++) {
                const __nv_bfloat16* src = srcs[op] + (size_t)rb[op] * K + k0;
                const uint32_t sb = st + op * OPB;
                #pragma unroll
                for (int it = 0; it < 2; it++) {
                    int ck = it * 256 + tid;        // 0..511
                    int r = ck >> 2, c = ck & 3;
                    cp16(sb + r * 80 + c * 16, src + (size_t)r * K + c * 8);
                }
            }
        }
        cp_commit();                                 // empty commit keeps group count aligned
    };

    wmma::fragment<wmma::accumulator, 16, 16, 16, float> acc[2][4];
    #pragma unroll
    for (int m = 0; m < 2; m++)
        #pragma unroll
        for (int n = 0; n < 4; n++) wmma::fill_fragment(acc[m][n], 0.f);

    load_chunk(0, 0); load_chunk(1, 1); load_chunk(2, 2);

    for (int i = 0; i < nch; i++) {
        cp_wait2();                                  // stage i resident
        __syncthreads();
        load_chunk(i + 3, (i + 3) & 3);
        const __nv_bfloat16* sb = (const __nv_bfloat16*)(smem + (size_t)(i & 3) * STG);
        const __nv_bfloat16* sAh_ = sb;
        const __nv_bfloat16* sAl_ = sb + OPE;
        const __nv_bfloat16* sBh_ = sb + 2 * OPE;
        const __nv_bfloat16* sBl_ = sb + 3 * OPE;
        #pragma unroll
        for (int kk = 0; kk < 2; kk++) {
            wmma::fragment<wmma::matrix_a, 16, 16, 16, __nv_bfloat16, wmma::row_major> fah[2], fal[2];
            wmma::fragment<wmma::matrix_b, 16, 16, 16, __nv_bfloat16, wmma::col_major> fbh[4], fbl[4];
            #pragma unroll
            for (int m = 0; m < 2; m++) {
                wmma::load_matrix_sync(fah[m], sAh_ + (wr*32 + m*16)*40 + kk*16, 40);
                wmma::load_matrix_sync(fal[m], sAl_ + (wr*32 + m*16)*40 + kk*16, 40);
            }
            #pragma unroll
            for (int n = 0; n < 4; n++) {
                wmma::load_matrix_sync(fbh[n], sBh_ + (wc*64 + n*16)*40 + kk*16, 40);
                wmma::load_matrix_sync(fbl[n], sBl_ + (wc*64 + n*16)*40 + kk*16, 40);
            }
            #pragma unroll
            for (int m = 0; m < 2; m++)
                #pragma unroll
                for (int n = 0; n < 4; n++) {
                    wmma::mma_sync(acc[m][n], fah[m], fbh[n], acc[m][n]);
                    wmma::mma_sync(acc[m][n], fal[m], fbh[n], acc[m][n]);
                    wmma::mma_sync(acc[m][n], fah[m], fbl[n], acc[m][n]);
                }
        }
    }

    if (mode == 0) {
        float* dst = Z + (size_t)(by * 128) * FH + bx * 128;
        #pragma unroll
        for (int m = 0; m < 2; m++)
            #pragma unroll
            for (int n = 0; n < 4; n++)
                wmma::store_matrix_sync(dst + (size_t)(wr*32 + m*16) * FH + wc*64 + n*16,
                                        acc[m][n], FH, wmma::mem_row_major);
        return;
    }

    // ---- fused LSTM gate epilogue ----
    __syncthreads();
    float* Zs = (float*)smem;
    #pragma unroll
    for (int m = 0; m < 2; m++)
        #pragma unroll
        for (int n = 0; n < 4; n++)
            wmma::store_matrix_sync(Zs + (wr*32 + m*16) * LDS_EP + wc*64 + n*16,
                                    acc[m][n], LDS_EP, wmma::mem_row_major);
    __syncthreads();

    const int rl = tid >> 1, half = tid & 1;
    const int row = by * 128 + rl;                  // batch index
    const int n0 = bx * 128 + half * 64;            // interleaved col base
    const int jb = n0 >> 2;                          // j base (16 j's)
    const float* zs = Zs + rl * LDS_EP + half * 64;
    const float4* zg = (const float4*)(Z + (size_t)row * FH + n0);
    const float4* bi4 = (const float4*)(biasI + n0);
    float* crow = cst + (size_t)row * HH + jb;
    const bool gath = seqlen && (seqlen[row] - 1 == t);

    float cn[16]; __nv_bfloat16 hb[16], lb[16];
    #pragma unroll
    for (int g = 0; g < 16; g++) {
        float4 zv = zg[g], bv = bi4[g];
        float vi = zs[g*4+0] + zv.x + bv.x;
        float vf = zs[g*4+1] + zv.y + bv.y;
        float vg = zs[g*4+2] + zv.z + bv.z;
        float vo = zs[g*4+3] + zv.w + bv.w;
        float ig = 1.f / (1.f + __expf(-vi));
        float fg = 1.f / (1.f + __expf(-vf));
        float gg = tanhf(vg);
        float og = 1.f / (1.f + __expf(-vo));
        float c_ = fg * crow[g] + ig * gg;
        cn[g] = c_;
        float hv = og * tanhf(c_);
        __nv_bfloat16 hi_ = __float2bfloat16(hv);
        hb[g] = hi_;
        lb[g] = __float2bfloat16(hv - __bfloat162float(hi_));
        if (gath) hidden[(size_t)row * HH + jb + g] = hv;
    }
    #pragma unroll
    for (int q = 0; q < 4; q++)
        ((float4*)crow)[q] = make_float4(cn[q*4], cn[q*4+1], cn[q*4+2], cn[q*4+3]);
    *(uint4*)(hh + (size_t)row * HH + jb)     = ((uint4*)hb)[0];
    *(uint4*)(hh + (size_t)row * HH + jb + 8) = ((uint4*)hb)[1];
    *(uint4*)(hl + (size_t)row * HH + jb)     = ((uint4*)lb)[0];
    *(uint4*)(hl + (size_t)row * HH + jb + 8) = ((uint4*)lb)[1];
}

// ------------- launch -------------
extern "C" void kernel_launch(void* const* d_in, const int* in_sizes, int n_in,
                              void* d_out, int out_size)
{
    const float* chars  = (const float*)d_in[0];
    const int*   seqlen = (const int*)  d_in[1];
    const float* W1 = (const float*)d_in[2];
    const float* U1 = (const float*)d_in[3];
    const float* b1 = (const float*)d_in[4];
    const float* W2 = (const float*)d_in[5];
    const float* U2 = (const float*)d_in[6];
    const float* b2 = (const float*)d_in[7];
    const float* Wd = (const float*)d_in[8];
    const float* bd = (const float*)d_in[9];
    float* out = (float*)d_out;

    cudaFuncSetAttribute(lstm_gemm, cudaFuncAttributeMaxDynamicSharedMemorySize, SMEM_DYN);

    float *Z, *c1, *c2, *hidden, *b1i, *b2i;
    __nv_bfloat16 *Xh, *Xl, *H1h, *H1l, *H2h, *H2l;
    __nv_bfloat16 *W1h, *W1l, *U1h, *U1l, *W2h, *W2l, *U2h, *U2l;
    cudaGetSymbolAddress((void**)&Z, d_Z);
    cudaGetSymbolAddress((void**)&c1, d_c1);   cudaGetSymbolAddress((void**)&c2, d_c2);
    cudaGetSymbolAddress((void**)&hidden, d_hidden);
    cudaGetSymbolAddress((void**)&b1i, d_b1i); cudaGetSymbolAddress((void**)&b2i, d_b2i);
    cudaGetSymbolAddress((void**)&Xh, d_Xh);   cudaGetSymbolAddress((void**)&Xl, d_Xl);
    cudaGetSymbolAddress((void**)&H1h, d_H1h); cudaGetSymbolAddress((void**)&H1l, d_H1l);
    cudaGetSymbolAddress((void**)&H2h, d_H2h); cudaGetSymbolAddress((void**)&H2l, d_H2l);
    cudaGetSymbolAddress((void**)&W1h, d_W1h); cudaGetSymbolAddress((void**)&W1l, d_W1l);
    cudaGetSymbolAddress((void**)&U1h, d_U1h); cudaGetSymbolAddress((void**)&U1l, d_U1l);
    cudaGetSymbolAddress((void**)&W2h, d_W2h); cudaGetSymbolAddress((void**)&W2l, d_W2l);
    cudaGetSymbolAddress((void**)&U2h, d_U2h); cudaGetSymbolAddress((void**)&U2l, d_U2l);

    split_w<<<(FH*DIN)/256, 256>>>(W1, W1h, W1l, DIN);
    split_w<<<(FH*HH)/256, 256>>>(U1, U1h, U1l, HH);
    split_w<<<(FH*HH)/256, 256>>>(W2, W2h, W2l, HH);
    split_w<<<(FH*HH)/256, 256>>>(U2, U2h, U2l, HH);
    interleave_bias<<<FH/256, 256>>>(b1, b1i);
    interleave_bias<<<FH/256, 256>>>(b2, b2i);
    split_chars<<<(TBROWS*64)/256, 256>>>(chars, Xh, Xl);
    init_states<<<(BB*HH)/256, 256>>>();

    const size_t HB = (size_t)BB * HH;
    dim3 gBig(FH/128, TBROWS/128);   // (32, 512)
    dim3 gStep(FH/128, BB/128);      // (32, 4)

    // layer 1 input transform: Z = X @ W1t^T
    lstm_gemm<<<gBig, 256, SMEM_DYN>>>(Xh, Xl, W1h, W1l, DIN, Z, 0,
                                       nullptr, nullptr, nullptr, nullptr, nullptr, nullptr, 0);
    // layer 1 recurrence (h_{t-1} = H1 block t, writes block t+1)
    for (int t = 0; t < TT; t++)
        lstm_gemm<<<gStep, 256, SMEM_DYN>>>(H1h + (size_t)t*HB, H1l + (size_t)t*HB,
                                            U1h, U1l, HH, Z + (size_t)t*BB*FH, 1,
                                            b1i, c1, H1h + (size_t)(t+1)*HB, H1l + (size_t)(t+1)*HB,
                                            nullptr, nullptr, t);
    // layer 2 input transform: Z = H1(1..T) @ W2t^T
    lstm_gemm<<<gBig, 256, SMEM_DYN>>>(H1h + HB, H1l + HB, W2h, W2l, HH, Z, 0,
                                       nullptr, nullptr, nullptr, nullptr, nullptr, nullptr, 0);
    // layer 2 recurrence + last-valid gather
    for (int t = 0; t < TT; t++)
        lstm_gemm<<<gStep, 256, SMEM_DYN>>>(H2h + (size_t)t*HB, H2l + (size_t)t*HB,
                                            U2h, U2l, HH, Z + (size_t)t*BB*FH, 1,
                                            b2i, c2, H2h + (size_t)(t+1)*HB, H2l + (size_t)(t+1)*HB,
                                            seqlen, hidden, t);

    dense_relu<<<BB, 128>>>(hidden, Wd, bd, out);
}